// round 13
// baseline (speedup 1.0000x reference)
#include <cuda_runtime.h>
#include <cuda_fp16.h>
#include <cstdint>

#define NN 50000
#define EE 800000
#define FIN 128
#define C1 128
#define NCLS 16
#define STASH1 64
#define STASH2 96
#define NB_SCAN 49   // ceil(50000/1024)
#define GB 148       // build-kernel grid: all-resident (<= SM count)

// ---------------- device scratch ----------------
__device__ int g_cnt[NN];              // zeroed by k_agg2 at end of each call (static zero at start)
__device__ int g_bar_ticket;           // monotonic grid-barrier ticket
__device__ int g_bar_flag;             // monotonic grid-barrier epoch flag
__device__ int g_cursor[NN];
__device__ int g_rowptr[NN + 1];
__device__ int g_bsum[64];
__device__ int g_boff[64];
__device__ int g_srcsorted[EE];
__device__ __half g_h1h[(size_t)NN * C1];
__device__ float g_als1[NN * 4];
__device__ float g_ald1[NN * 4];
__device__ float g_h2[NN * NCLS];
__device__ float g_als2[NN];
__device__ float g_ald2[NN];

__device__ __forceinline__ float lrelu(float v) { return v > 0.f ? v : 0.2f * v; }

__device__ __forceinline__ float totf32(float x) {
    uint32_t u;
    asm("cvt.rna.tf32.f32 %0, %1;" : "=r"(u) : "f"(x));
    return __uint_as_float(u);
}

__device__ __forceinline__ void mma_tf32(float& c0, float& c1, float& c2, float& c3,
                                         uint32_t a0, uint32_t a1, uint32_t a2, uint32_t a3,
                                         uint32_t b0, uint32_t b1) {
    asm volatile(
        "mma.sync.aligned.m16n8k8.row.col.f32.tf32.tf32.f32 "
        "{%0,%1,%2,%3}, {%4,%5,%6,%7}, {%8,%9}, {%0,%1,%2,%3};"
        : "+f"(c0), "+f"(c1), "+f"(c2), "+f"(c3)
        : "r"(a0), "r"(a1), "r"(a2), "r"(a3), "r"(b0), "r"(b1));
}

// grid-wide barrier: monotonic ticket/flag, graph-replay safe (no reset needed)
__device__ __forceinline__ void grid_barrier() {
    __threadfence();
    __syncthreads();
    if (threadIdx.x == 0) {
        int e = atomicAdd(&g_bar_ticket, 1);
        int t = e / GB + 1;
        if ((e % GB) == GB - 1) atomicExch(&g_bar_flag, t);
        while (atomicAdd(&g_bar_flag, 0) < t) {}
        __threadfence();
    }
    __syncthreads();
}

// ---------------- fused CSR build: hist -> scan -> scatter, one kernel ----------------
__global__ void __launch_bounds__(1024) k_build(const int* __restrict__ ei) {
    int tid = threadIdx.x;
    int lane = tid & 31, w = tid >> 5;
    int gt = blockIdx.x * 1024 + tid;
    const int NT = GB * 1024;
    __shared__ int wt[32];

    // P1: histogram (g_cnt pre-zeroed by previous call's agg2 / static init)
    for (int c = gt; c < EE / 8; c += NT) {
        int4 d0 = ((const int4*)(ei + EE))[2 * c];
        int4 d1 = ((const int4*)(ei + EE))[2 * c + 1];
        atomicAdd(&g_cnt[d0.x], 1); atomicAdd(&g_cnt[d0.y], 1);
        atomicAdd(&g_cnt[d0.z], 1); atomicAdd(&g_cnt[d0.w], 1);
        atomicAdd(&g_cnt[d1.x], 1); atomicAdd(&g_cnt[d1.y], 1);
        atomicAdd(&g_cnt[d1.z], 1); atomicAdd(&g_cnt[d1.w], 1);
    }
    grid_barrier();

    // P2a: per-block local scans (blocks 0..48 own 1024 nodes each)
    int incl = 0, v = 0;
    if (blockIdx.x < NB_SCAN) {
        int i = blockIdx.x * 1024 + tid;
        v = (i < NN) ? g_cnt[i] : 0;
        int xv = v;
#pragma unroll
        for (int o = 1; o < 32; o <<= 1) {
            int t = __shfl_up_sync(0xffffffffu, xv, o);
            if (lane >= o) xv += t;
        }
        if (lane == 31) wt[w] = xv;
        __syncthreads();
        if (w == 0) {
            int y = wt[lane];
#pragma unroll
            for (int o = 1; o < 32; o <<= 1) {
                int t = __shfl_up_sync(0xffffffffu, y, o);
                if (lane >= o) y += t;
            }
            wt[lane] = y;
        }
        __syncthreads();
        incl = xv + (w ? wt[w - 1] : 0);
        if (tid == 1023) g_bsum[blockIdx.x] = incl;
    }
    grid_barrier();

    // P2b: single warp scans the 49 block sums
    if (blockIdx.x == 0 && tid < 32) {
        int v0 = (tid < NB_SCAN) ? g_bsum[tid] : 0;
        int v1 = (tid + 32 < NB_SCAN) ? g_bsum[tid + 32] : 0;
        int x0 = v0;
#pragma unroll
        for (int o = 1; o < 32; o <<= 1) {
            int t = __shfl_up_sync(0xffffffffu, x0, o);
            if (tid >= o) x0 += t;
        }
        int t0 = __shfl_sync(0xffffffffu, x0, 31);
        int x1 = v1;
#pragma unroll
        for (int o = 1; o < 32; o <<= 1) {
            int t = __shfl_up_sync(0xffffffffu, x1, o);
            if (tid >= o) x1 += t;
        }
        g_boff[tid] = x0 - v0;
        g_boff[tid + 32] = t0 + x1 - v1;
        if (tid == 31) g_rowptr[NN] = t0 + x1;
    }
    grid_barrier();

    // P2c: finalize rowptr + cursor
    if (blockIdx.x < NB_SCAN) {
        int i = blockIdx.x * 1024 + tid;
        if (i < NN) {
            int r = incl - v + g_boff[blockIdx.x];
            g_rowptr[i] = r;
            g_cursor[i] = r;
        }
    }
    grid_barrier();

    // P3: scatter
    for (int c = gt; c < EE / 8; c += NT) {
        int4 s0 = ((const int4*)ei)[2 * c];
        int4 s1 = ((const int4*)ei)[2 * c + 1];
        int4 d0 = ((const int4*)(ei + EE))[2 * c];
        int4 d1 = ((const int4*)(ei + EE))[2 * c + 1];
        g_srcsorted[atomicAdd(&g_cursor[d0.x], 1)] = s0.x;
        g_srcsorted[atomicAdd(&g_cursor[d0.y], 1)] = s0.y;
        g_srcsorted[atomicAdd(&g_cursor[d0.z], 1)] = s0.z;
        g_srcsorted[atomicAdd(&g_cursor[d0.w], 1)] = s0.w;
        g_srcsorted[atomicAdd(&g_cursor[d1.x], 1)] = s1.x;
        g_srcsorted[atomicAdd(&g_cursor[d1.y], 1)] = s1.y;
        g_srcsorted[atomicAdd(&g_cursor[d1.z], 1)] = s1.z;
        g_srcsorted[atomicAdd(&g_cursor[d1.w], 1)] = s1.w;
    }
}

// ---------------- GEMM1 (tf32 tensor) + fused al1, fp16 h1 out ----------------
#define G1_SMEM ((128 * 132 + 64 * 132 + 256) * 4)

__global__ void __launch_bounds__(128) k_gemm1(
    const float* __restrict__ x, const float* __restrict__ W,
    const float* __restrict__ asrc, const float* __restrict__ adst) {
    extern __shared__ float sm[];
    float* ws = sm;
    float* xs = sm + 128 * 132;
    float* sa = xs + 64 * 132;
    float* sd = sa + 128;

    int tid = threadIdx.x;
    int lane = tid & 31, wid = tid >> 5;
    int g = lane >> 2, q = lane & 3;
    int r0 = blockIdx.x * 64;

    for (int i = tid; i < 128 * 32; i += 128) {
        int k = i >> 5, nq = (i & 31) * 4;
        float4 v = *(const float4*)&W[k * C1 + nq];
        *(float4*)&ws[k * 132 + nq] =
            make_float4(totf32(v.x), totf32(v.y), totf32(v.z), totf32(v.w));
    }
    for (int i = tid; i < 64 * 32; i += 128) {
        int r = i >> 5, kq = (i & 31) * 4;
        float4 v = (r0 + r < NN) ? *(const float4*)&x[(size_t)(r0 + r) * FIN + kq]
                                 : make_float4(0.f, 0.f, 0.f, 0.f);
        *(float4*)&xs[r * 132 + kq] =
            make_float4(totf32(v.x), totf32(v.y), totf32(v.z), totf32(v.w));
    }
    if (tid < 128) { sa[tid] = asrc[tid]; sd[tid] = adst[tid]; }
    __syncthreads();

    int r0l = wid * 16 + g;
    int r1l = r0l + 8;

    float c[16][4];
#pragma unroll
    for (int j = 0; j < 16; j++) { c[j][0] = c[j][1] = c[j][2] = c[j][3] = 0.f; }

#pragma unroll
    for (int t = 0; t < 16; t++) {
        int k0 = t * 8;
        uint32_t a0 = __float_as_uint(xs[r0l * 132 + k0 + q]);
        uint32_t a1 = __float_as_uint(xs[r1l * 132 + k0 + q]);
        uint32_t a2 = __float_as_uint(xs[r0l * 132 + k0 + q + 4]);
        uint32_t a3 = __float_as_uint(xs[r1l * 132 + k0 + q + 4]);
#pragma unroll
        for (int j = 0; j < 16; j++) {
            uint32_t b0 = __float_as_uint(ws[(k0 + q) * 132 + j * 8 + g]);
            uint32_t b1 = __float_as_uint(ws[(k0 + q + 4) * 132 + j * 8 + g]);
            mma_tf32(c[j][0], c[j][1], c[j][2], c[j][3], a0, a1, a2, a3, b0, b1);
        }
    }

    int gr0 = r0 + r0l, gr1 = r0 + r1l;
    float ps0[4] = {0, 0, 0, 0}, pd0[4] = {0, 0, 0, 0};
    float ps1[4] = {0, 0, 0, 0}, pd1[4] = {0, 0, 0, 0};
#pragma unroll
    for (int j = 0; j < 16; j++) {
        int col = j * 8 + 2 * q;
        float a0s = sa[col], a1s = sa[col + 1];
        float a0d = sd[col], a1d = sd[col + 1];
        int h = j >> 2;
        ps0[h] += c[j][0] * a0s + c[j][1] * a1s;
        pd0[h] += c[j][0] * a0d + c[j][1] * a1d;
        ps1[h] += c[j][2] * a0s + c[j][3] * a1s;
        pd1[h] += c[j][2] * a0d + c[j][3] * a1d;
        if (gr0 < NN) *(__half2*)&g_h1h[(size_t)gr0 * C1 + col] = __floats2half2_rn(c[j][0], c[j][1]);
        if (gr1 < NN) *(__half2*)&g_h1h[(size_t)gr1 * C1 + col] = __floats2half2_rn(c[j][2], c[j][3]);
    }
#pragma unroll
    for (int h = 0; h < 4; h++) {
        ps0[h] += __shfl_xor_sync(0xffffffffu, ps0[h], 1);
        ps0[h] += __shfl_xor_sync(0xffffffffu, ps0[h], 2);
        pd0[h] += __shfl_xor_sync(0xffffffffu, pd0[h], 1);
        pd0[h] += __shfl_xor_sync(0xffffffffu, pd0[h], 2);
        ps1[h] += __shfl_xor_sync(0xffffffffu, ps1[h], 1);
        ps1[h] += __shfl_xor_sync(0xffffffffu, ps1[h], 2);
        pd1[h] += __shfl_xor_sync(0xffffffffu, pd1[h], 1);
        pd1[h] += __shfl_xor_sync(0xffffffffu, pd1[h], 2);
    }
    if (q == 0) {
#pragma unroll
        for (int h = 0; h < 4; h++) {
            if (gr0 < NN) { g_als1[gr0 * 4 + h] = ps0[h]; g_ald1[gr0 * 4 + h] = pd0[h]; }
            if (gr1 < NN) { g_als1[gr1 * 4 + h] = ps1[h]; g_ald1[gr1 * 4 + h] = pd1[h]; }
        }
    }
}

// ---------------- FUSED: layer-1 aggregate (+bias+ELU, to smem) + GEMM2 tf32 + al2 ----------------
#define FU_HS    0
#define FU_WS2   (64 * 132)
#define FU_SA    (FU_WS2 + 128 * 24)
#define FU_SD    (FU_SA + 16)
#define FU_SE    (FU_SD + 16)
#define FU_SS    (FU_SE + 8 * STASH1 * 4)
#define FU_SMEM  ((FU_SS + 8 * STASH1) * 4)

__global__ void __launch_bounds__(256) k_agg1g2(
    const float* __restrict__ b1, const float* __restrict__ W2,
    const float* __restrict__ as2, const float* __restrict__ ad2) {
    extern __shared__ float sm[];
    float* hs = sm + FU_HS;
    float* ws2 = sm + FU_WS2;
    float* sa = sm + FU_SA;
    float* sd = sm + FU_SD;
    int tid = threadIdx.x;
    int lane = tid & 31, w = tid >> 5;
    float* se = sm + FU_SE + w * (STASH1 * 4);
    int* ss = (int*)(sm + FU_SS) + w * STASH1;
    int n0 = blockIdx.x * 64;

    for (int i = tid; i < FIN * NCLS; i += 256) {
        int k = i >> 4, nn = i & 15;
        ws2[k * 24 + nn] = totf32(W2[i]);
    }
    if (tid < 16) { sa[tid] = as2[tid]; sd[tid] = ad2[tid]; }

    float4 bb = __ldg((const float4*)&b1[lane * 4]);

    // ---- Phase A: aggregate 8 nodes per warp ----
    for (int j = 0; j < 8; j++) {
        int r = j * 8 + w;
        int n = n0 + r;
        if (n >= NN) break;
        int base = g_rowptr[n];
        int deg = g_rowptr[n + 1] - base;
        int tot = deg + 1;
        float4 ald = *(const float4*)&g_ald1[n * 4];
        bool st = (tot <= STASH1);

        float d0 = 0.f, d1 = 0.f, d2 = 0.f, d3 = 0.f;
        if (st) {
            for (int i = lane; i < tot; i += 32) {
                int s = (i < deg) ? g_srcsorted[base + i] : n;
                ss[i] = s;
                float4 as = *(const float4*)&g_als1[s * 4];
                float x0 = __expf(lrelu(as.x + ald.x));
                float x1 = __expf(lrelu(as.y + ald.y));
                float x2 = __expf(lrelu(as.z + ald.z));
                float x3 = __expf(lrelu(as.w + ald.w));
                d0 += x0; d1 += x1; d2 += x2; d3 += x3;
                *(float4*)&se[i * 4] = make_float4(x0, x1, x2, x3);
            }
        } else {
            for (int i = lane; i < tot; i += 32) {
                int s = (i < deg) ? g_srcsorted[base + i] : n;
                float4 as = *(const float4*)&g_als1[s * 4];
                d0 += __expf(lrelu(as.x + ald.x));
                d1 += __expf(lrelu(as.y + ald.y));
                d2 += __expf(lrelu(as.z + ald.z));
                d3 += __expf(lrelu(as.w + ald.w));
            }
        }
#pragma unroll
        for (int o = 16; o >= 1; o >>= 1) {
            d0 += __shfl_xor_sync(0xffffffffu, d0, o);
            d1 += __shfl_xor_sync(0xffffffffu, d1, o);
            d2 += __shfl_xor_sync(0xffffffffu, d2, o);
            d3 += __shfl_xor_sync(0xffffffffu, d3, o);
        }
        __syncwarp();

        int head = lane >> 3;
        float dh = head == 0 ? d0 : (head == 1 ? d1 : (head == 2 ? d2 : d3));
        float inv = 1.f / dh;

        float a0 = 0.f, a1 = 0.f, a2 = 0.f, a3 = 0.f;
        if (st) {
#pragma unroll 4
            for (int i = 0; i < tot; i++) {
                float alpha = se[i * 4 + head] * inv;
                int s = ss[i];
                uint2 raw = *(const uint2*)&g_h1h[(size_t)s * C1 + lane * 4];
                float2 f0 = __half22float2(*reinterpret_cast<__half2*>(&raw.x));
                float2 f1 = __half22float2(*reinterpret_cast<__half2*>(&raw.y));
                a0 += f0.x * alpha; a1 += f0.y * alpha;
                a2 += f1.x * alpha; a3 += f1.y * alpha;
            }
        } else {
            for (int i = 0; i < tot; i++) {
                int s = (i < deg) ? g_srcsorted[base + i] : n;
                float4 as = *(const float4*)&g_als1[s * 4];
                float ev = head == 0 ? (as.x + ald.x) : head == 1 ? (as.y + ald.y)
                         : head == 2 ? (as.z + ald.z) : (as.w + ald.w);
                float alpha = __expf(lrelu(ev)) * inv;
                uint2 raw = *(const uint2*)&g_h1h[(size_t)s * C1 + lane * 4];
                float2 f0 = __half22float2(*reinterpret_cast<__half2*>(&raw.x));
                float2 f1 = __half22float2(*reinterpret_cast<__half2*>(&raw.y));
                a0 += f0.x * alpha; a1 += f0.y * alpha;
                a2 += f1.x * alpha; a3 += f1.y * alpha;
            }
        }

        float v0 = a0 + bb.x, v1 = a1 + bb.y, v2 = a2 + bb.z, v3 = a3 + bb.w;
        v0 = v0 > 0.f ? v0 : (__expf(v0) - 1.f);
        v1 = v1 > 0.f ? v1 : (__expf(v1) - 1.f);
        v2 = v2 > 0.f ? v2 : (__expf(v2) - 1.f);
        v3 = v3 > 0.f ? v3 : (__expf(v3) - 1.f);
        *(float4*)&hs[r * 132 + lane * 4] =
            make_float4(totf32(v0), totf32(v1), totf32(v2), totf32(v3));
    }
    __syncthreads();

    // ---- Phase B: tf32 MMA gemm2 + fused al2 (warps 0-3) ----
    if (w < 4) {
        int g = lane >> 2, q = lane & 3;
        int r0 = w * 16;
        float c[2][4];
        c[0][0] = c[0][1] = c[0][2] = c[0][3] = 0.f;
        c[1][0] = c[1][1] = c[1][2] = c[1][3] = 0.f;

#pragma unroll
        for (int t = 0; t < 16; t++) {
            int k0 = t * 8;
            uint32_t a0 = __float_as_uint(hs[(r0 + g) * 132 + k0 + q]);
            uint32_t a1 = __float_as_uint(hs[(r0 + g + 8) * 132 + k0 + q]);
            uint32_t a2 = __float_as_uint(hs[(r0 + g) * 132 + k0 + q + 4]);
            uint32_t a3 = __float_as_uint(hs[(r0 + g + 8) * 132 + k0 + q + 4]);
#pragma unroll
            for (int nt = 0; nt < 2; nt++) {
                uint32_t b0 = __float_as_uint(ws2[(k0 + q) * 24 + nt * 8 + g]);
                uint32_t b1 = __float_as_uint(ws2[(k0 + q + 4) * 24 + nt * 8 + g]);
                mma_tf32(c[nt][0], c[nt][1], c[nt][2], c[nt][3], a0, a1, a2, a3, b0, b1);
            }
        }

        int row0 = n0 + r0 + g, row1 = row0 + 8;
        float s0 = 0.f, e0 = 0.f, s1 = 0.f, e1 = 0.f;
#pragma unroll
        for (int nt = 0; nt < 2; nt++) {
            int col = nt * 8 + 2 * q;
            if (row0 < NN) *(float2*)&g_h2[row0 * NCLS + col] = make_float2(c[nt][0], c[nt][1]);
            if (row1 < NN) *(float2*)&g_h2[row1 * NCLS + col] = make_float2(c[nt][2], c[nt][3]);
            float wa0 = sa[col], wa1 = sa[col + 1];
            float wd0 = sd[col], wd1 = sd[col + 1];
            s0 += c[nt][0] * wa0 + c[nt][1] * wa1;
            e0 += c[nt][0] * wd0 + c[nt][1] * wd1;
            s1 += c[nt][2] * wa0 + c[nt][3] * wa1;
            e1 += c[nt][2] * wd0 + c[nt][3] * wd1;
        }
        s0 += __shfl_xor_sync(0xffffffffu, s0, 1); s0 += __shfl_xor_sync(0xffffffffu, s0, 2);
        e0 += __shfl_xor_sync(0xffffffffu, e0, 1); e0 += __shfl_xor_sync(0xffffffffu, e0, 2);
        s1 += __shfl_xor_sync(0xffffffffu, s1, 1); s1 += __shfl_xor_sync(0xffffffffu, s1, 2);
        e1 += __shfl_xor_sync(0xffffffffu, e1, 1); e1 += __shfl_xor_sync(0xffffffffu, e1, 2);
        if (q == 0) {
            if (row0 < NN) { g_als2[row0] = s0; g_ald2[row0] = e0; }
            if (row1 < NN) { g_als2[row1] = s1; g_ald2[row1] = e1; }
        }
    }
}

// ---------------- layer-2 softmax-aggregate (+bias+log_softmax); zeroes g_cnt ----------------
__global__ void k_agg2(const float* __restrict__ b2, float* __restrict__ out) {
    __shared__ float se[8][STASH2];
    __shared__ int ss[8][STASH2];
    int lane = threadIdx.x & 31, w = threadIdx.x >> 5;
    int n = blockIdx.x * 8 + w;
    if (n >= NN) return;
    int base = g_rowptr[n];
    int deg = g_rowptr[n + 1] - base;
    int tot = deg + 1;
    float ald = g_ald2[n];
    bool st = (tot <= STASH2);

    float den = 0.f;
    if (st) {
        for (int i = lane; i < tot; i += 32) {
            int s = (i < deg) ? g_srcsorted[base + i] : n;
            ss[w][i] = s;
            float ex = __expf(lrelu(g_als2[s] + ald));
            se[w][i] = ex;
            den += ex;
        }
    } else {
        for (int i = lane; i < tot; i += 32) {
            int s = (i < deg) ? g_srcsorted[base + i] : n;
            den += __expf(lrelu(g_als2[s] + ald));
        }
    }
#pragma unroll
    for (int o = 16; o >= 1; o >>= 1)
        den += __shfl_xor_sync(0xffffffffu, den, o);
    __syncwarp();
    float inv = 1.f / den;

    float acc = 0.f;
    if (st) {
#pragma unroll 4
        for (int i = 0; i < tot; i++) {
            float alpha = se[w][i] * inv;
            int s = ss[w][i];
            if (lane < NCLS) acc += g_h2[s * NCLS + lane] * alpha;
        }
    } else {
        for (int i = 0; i < tot; i++) {
            int s = (i < deg) ? g_srcsorted[base + i] : n;
            float alpha = __expf(lrelu(g_als2[s] + ald)) * inv;
            if (lane < NCLS) acc += g_h2[s * NCLS + lane] * alpha;
        }
    }

    float v = (lane < NCLS) ? (acc + __ldg(&b2[lane])) : -1e30f;
    float mm = v;
#pragma unroll
    for (int o = 8; o >= 1; o >>= 1)
        mm = fmaxf(mm, __shfl_xor_sync(0xffffffffu, mm, o, 16));
    float ex = __expf(v - mm);
    float sum = ex;
#pragma unroll
    for (int o = 8; o >= 1; o >>= 1)
        sum += __shfl_xor_sync(0xffffffffu, sum, o, 16);
    float res = v - mm - __logf(sum);
    if (lane < NCLS) out[n * NCLS + lane] = res;
    // restore pre-call state for next replay
    if (lane == 0) g_cnt[n] = 0;
}

// ---------------- launch ----------------
extern "C" void kernel_launch(void* const* d_in, const int* in_sizes, int n_in,
                              void* d_out, int out_size) {
    const float* x   = (const float*)d_in[0];
    const int*   ei  = (const int*)d_in[1];
    const float* W1  = (const float*)d_in[2];
    const float* as1 = (const float*)d_in[3];
    const float* ad1 = (const float*)d_in[4];
    const float* b1  = (const float*)d_in[5];
    const float* W2  = (const float*)d_in[6];
    const float* as2 = (const float*)d_in[7];
    const float* ad2 = (const float*)d_in[8];
    const float* b2  = (const float*)d_in[9];
    float* out = (float*)d_out;

    static bool inited = false;
    static cudaStream_t s2 = nullptr;
    static cudaEvent_t evFork = nullptr, evJoin = nullptr;
    if (!inited) {
        inited = true;
        cudaFuncSetAttribute(k_gemm1, cudaFuncAttributeMaxDynamicSharedMemorySize, G1_SMEM);
        cudaFuncSetAttribute(k_agg1g2, cudaFuncAttributeMaxDynamicSharedMemorySize, FU_SMEM);
        cudaStreamCreateWithFlags(&s2, cudaStreamNonBlocking);
        cudaEventCreateWithFlags(&evFork, cudaEventDisableTiming);
        cudaEventCreateWithFlags(&evJoin, cudaEventDisableTiming);
    }

    // fork: gemm1 runs on s2 in parallel with the fused CSR build
    cudaEventRecord(evFork, 0);
    cudaStreamWaitEvent(s2, evFork, 0);
    k_gemm1<<<(NN + 63) / 64, 128, G1_SMEM, s2>>>(x, W1, as1, ad1);
    cudaEventRecord(evJoin, s2);

    // CSR build: single kernel (hist + scan + scatter via grid barriers)
    k_build<<<GB, 1024>>>(ei);

    // join
    cudaStreamWaitEvent(0, evJoin, 0);
    k_agg1g2<<<(NN + 63) / 64, 256, FU_SMEM>>>(b1, W2, as2, ad2);
    k_agg2<<<(NN + 7) / 8, 256>>>(b2, out);
}

// round 15
// speedup vs baseline: 1.2525x; 1.2525x over previous
#include <cuda_runtime.h>
#include <cuda_fp16.h>
#include <cstdint>

#define NN 50000
#define EE 800000
#define FIN 128
#define C1 128
#define NCLS 16
#define STASH1 64
#define STASH2 96
#define NB_SCAN 49   // ceil(50000/1024)

// ---------------- device scratch ----------------
__device__ int g_cnt[NN + 2];          // [NN]=scan ticket, [NN+1]=boff-ready flag
__device__ int g_cursor[NN];
__device__ int g_rowptr[NN + 1];
__device__ int g_bsum[64];
__device__ int g_boff[64];
__device__ int g_srcsorted[EE];
__device__ __half g_h1h[(size_t)NN * C1];
__device__ float g_als1[NN * 4];
__device__ float g_ald1[NN * 4];
__device__ float g_h2[NN * NCLS];
__device__ float g_als2[NN];
__device__ float g_ald2[NN];

__device__ __forceinline__ float lrelu(float v) { return v > 0.f ? v : 0.2f * v; }

__device__ __forceinline__ float totf32(float x) {
    uint32_t u;
    asm("cvt.rna.tf32.f32 %0, %1;" : "=r"(u) : "f"(x));
    return __uint_as_float(u);
}

__device__ __forceinline__ void mma_tf32(float& c0, float& c1, float& c2, float& c3,
                                         uint32_t a0, uint32_t a1, uint32_t a2, uint32_t a3,
                                         uint32_t b0, uint32_t b1) {
    asm volatile(
        "mma.sync.aligned.m16n8k8.row.col.f32.tf32.tf32.f32 "
        "{%0,%1,%2,%3}, {%4,%5,%6,%7}, {%8,%9}, {%0,%1,%2,%3};"
        : "+f"(c0), "+f"(c1), "+f"(c2), "+f"(c3)
        : "r"(a0), "r"(a1), "r"(a2), "r"(a3), "r"(b0), "r"(b1));
}

// ---------------- CSR build ----------------
__global__ void k_hist(const int* __restrict__ ei) {
    int t = blockIdx.x * blockDim.x + threadIdx.x;
    if (t < EE / 8) {
        int4 d0 = ((const int4*)(ei + EE))[2 * t];
        int4 d1 = ((const int4*)(ei + EE))[2 * t + 1];
        atomicAdd(&g_cnt[d0.x], 1); atomicAdd(&g_cnt[d0.y], 1);
        atomicAdd(&g_cnt[d0.z], 1); atomicAdd(&g_cnt[d0.w], 1);
        atomicAdd(&g_cnt[d1.x], 1); atomicAdd(&g_cnt[d1.y], 1);
        atomicAdd(&g_cnt[d1.z], 1); atomicAdd(&g_cnt[d1.w], 1);
    }
}

__global__ void k_scan() {
    __shared__ int wt[32];
    __shared__ int s_last;
    __shared__ int s_off;
    int tid = threadIdx.x, lane = tid & 31, w = tid >> 5;
    int i = blockIdx.x * 1024 + tid;
    int v = (i < NN) ? g_cnt[i] : 0;
    int xv = v;
#pragma unroll
    for (int o = 1; o < 32; o <<= 1) {
        int t = __shfl_up_sync(0xffffffffu, xv, o);
        if (lane >= o) xv += t;
    }
    if (lane == 31) wt[w] = xv;
    __syncthreads();
    if (w == 0) {
        int y = wt[lane];
#pragma unroll
        for (int o = 1; o < 32; o <<= 1) {
            int t = __shfl_up_sync(0xffffffffu, y, o);
            if (lane >= o) y += t;
        }
        wt[lane] = y;
    }
    __syncthreads();
    int incl = xv + (w ? wt[w - 1] : 0);
    if (tid == 1023) g_bsum[blockIdx.x] = incl;
    __threadfence();
    if (tid == 0) s_last = (atomicAdd(&g_cnt[NN], 1) == NB_SCAN - 1);
    __syncthreads();
    if (s_last) {
        if (tid < 32) {
            int v0 = (tid < NB_SCAN) ? g_bsum[tid] : 0;
            int v1 = (tid + 32 < NB_SCAN) ? g_bsum[tid + 32] : 0;
            int x0 = v0;
#pragma unroll
            for (int o = 1; o < 32; o <<= 1) {
                int t = __shfl_up_sync(0xffffffffu, x0, o);
                if (tid >= o) x0 += t;
            }
            int t0 = __shfl_sync(0xffffffffu, x0, 31);
            int x1 = v1;
#pragma unroll
            for (int o = 1; o < 32; o <<= 1) {
                int t = __shfl_up_sync(0xffffffffu, x1, o);
                if (tid >= o) x1 += t;
            }
            g_boff[tid] = x0 - v0;
            g_boff[tid + 32] = t0 + x1 - v1;
            if (tid == 31) g_rowptr[NN] = t0 + x1;
        }
        __threadfence();
        __syncthreads();
        if (tid == 0) atomicExch(&g_cnt[NN + 1], 1);
    }
    if (tid == 0) {
        while (atomicAdd(&g_cnt[NN + 1], 0) == 0) {}
        s_off = atomicAdd(&g_boff[blockIdx.x], 0);
    }
    __syncthreads();
    if (i < NN) {
        int r = incl - v + s_off;
        g_rowptr[i] = r;
        g_cursor[i] = r;
    }
}

__global__ void k_scatter(const int* __restrict__ ei) {
    int t = blockIdx.x * blockDim.x + threadIdx.x;
    if (t < EE / 8) {
        int4 s0 = ((const int4*)ei)[2 * t];
        int4 s1 = ((const int4*)ei)[2 * t + 1];
        int4 d0 = ((const int4*)(ei + EE))[2 * t];
        int4 d1 = ((const int4*)(ei + EE))[2 * t + 1];
        g_srcsorted[atomicAdd(&g_cursor[d0.x], 1)] = s0.x;
        g_srcsorted[atomicAdd(&g_cursor[d0.y], 1)] = s0.y;
        g_srcsorted[atomicAdd(&g_cursor[d0.z], 1)] = s0.z;
        g_srcsorted[atomicAdd(&g_cursor[d0.w], 1)] = s0.w;
        g_srcsorted[atomicAdd(&g_cursor[d1.x], 1)] = s1.x;
        g_srcsorted[atomicAdd(&g_cursor[d1.y], 1)] = s1.y;
        g_srcsorted[atomicAdd(&g_cursor[d1.z], 1)] = s1.z;
        g_srcsorted[atomicAdd(&g_cursor[d1.w], 1)] = s1.w;
    }
}

// ---------------- GEMM1 (tf32 tensor) + fused al1, fp16 h1 out ----------------
#define G1_SMEM ((128 * 132 + 64 * 132 + 256) * 4)

__global__ void __launch_bounds__(128) k_gemm1(
    const float* __restrict__ x, const float* __restrict__ W,
    const float* __restrict__ asrc, const float* __restrict__ adst) {
    extern __shared__ float sm[];
    float* ws = sm;
    float* xs = sm + 128 * 132;
    float* sa = xs + 64 * 132;
    float* sd = sa + 128;

    int tid = threadIdx.x;
    int lane = tid & 31, wid = tid >> 5;
    int g = lane >> 2, q = lane & 3;
    int r0 = blockIdx.x * 64;

    for (int i = tid; i < 128 * 32; i += 128) {
        int k = i >> 5, nq = (i & 31) * 4;
        float4 v = *(const float4*)&W[k * C1 + nq];
        *(float4*)&ws[k * 132 + nq] =
            make_float4(totf32(v.x), totf32(v.y), totf32(v.z), totf32(v.w));
    }
    for (int i = tid; i < 64 * 32; i += 128) {
        int r = i >> 5, kq = (i & 31) * 4;
        float4 v = (r0 + r < NN) ? *(const float4*)&x[(size_t)(r0 + r) * FIN + kq]
                                 : make_float4(0.f, 0.f, 0.f, 0.f);
        *(float4*)&xs[r * 132 + kq] =
            make_float4(totf32(v.x), totf32(v.y), totf32(v.z), totf32(v.w));
    }
    if (tid < 128) { sa[tid] = asrc[tid]; sd[tid] = adst[tid]; }
    __syncthreads();

    int r0l = wid * 16 + g;
    int r1l = r0l + 8;

    float c[16][4];
#pragma unroll
    for (int j = 0; j < 16; j++) { c[j][0] = c[j][1] = c[j][2] = c[j][3] = 0.f; }

#pragma unroll
    for (int t = 0; t < 16; t++) {
        int k0 = t * 8;
        uint32_t a0 = __float_as_uint(xs[r0l * 132 + k0 + q]);
        uint32_t a1 = __float_as_uint(xs[r1l * 132 + k0 + q]);
        uint32_t a2 = __float_as_uint(xs[r0l * 132 + k0 + q + 4]);
        uint32_t a3 = __float_as_uint(xs[r1l * 132 + k0 + q + 4]);
#pragma unroll
        for (int j = 0; j < 16; j++) {
            uint32_t b0 = __float_as_uint(ws[(k0 + q) * 132 + j * 8 + g]);
            uint32_t b1 = __float_as_uint(ws[(k0 + q + 4) * 132 + j * 8 + g]);
            mma_tf32(c[j][0], c[j][1], c[j][2], c[j][3], a0, a1, a2, a3, b0, b1);
        }
    }

    int gr0 = r0 + r0l, gr1 = r0 + r1l;
    float ps0[4] = {0, 0, 0, 0}, pd0[4] = {0, 0, 0, 0};
    float ps1[4] = {0, 0, 0, 0}, pd1[4] = {0, 0, 0, 0};
#pragma unroll
    for (int j = 0; j < 16; j++) {
        int col = j * 8 + 2 * q;
        float a0s = sa[col], a1s = sa[col + 1];
        float a0d = sd[col], a1d = sd[col + 1];
        int h = j >> 2;
        ps0[h] += c[j][0] * a0s + c[j][1] * a1s;
        pd0[h] += c[j][0] * a0d + c[j][1] * a1d;
        ps1[h] += c[j][2] * a0s + c[j][3] * a1s;
        pd1[h] += c[j][2] * a0d + c[j][3] * a1d;
        if (gr0 < NN) *(__half2*)&g_h1h[(size_t)gr0 * C1 + col] = __floats2half2_rn(c[j][0], c[j][1]);
        if (gr1 < NN) *(__half2*)&g_h1h[(size_t)gr1 * C1 + col] = __floats2half2_rn(c[j][2], c[j][3]);
    }
#pragma unroll
    for (int h = 0; h < 4; h++) {
        ps0[h] += __shfl_xor_sync(0xffffffffu, ps0[h], 1);
        ps0[h] += __shfl_xor_sync(0xffffffffu, ps0[h], 2);
        pd0[h] += __shfl_xor_sync(0xffffffffu, pd0[h], 1);
        pd0[h] += __shfl_xor_sync(0xffffffffu, pd0[h], 2);
        ps1[h] += __shfl_xor_sync(0xffffffffu, ps1[h], 1);
        ps1[h] += __shfl_xor_sync(0xffffffffu, ps1[h], 2);
        pd1[h] += __shfl_xor_sync(0xffffffffu, pd1[h], 1);
        pd1[h] += __shfl_xor_sync(0xffffffffu, pd1[h], 2);
    }
    if (q == 0) {
#pragma unroll
        for (int h = 0; h < 4; h++) {
            if (gr0 < NN) { g_als1[gr0 * 4 + h] = ps0[h]; g_ald1[gr0 * 4 + h] = pd0[h]; }
            if (gr1 < NN) { g_als1[gr1 * 4 + h] = ps1[h]; g_ald1[gr1 * 4 + h] = pd1[h]; }
        }
    }
}

// ---------------- FUSED: layer-1 aggregate (+bias+ELU, to smem) + GEMM2 tf32 + al2 ----------------
#define FU_HS    0
#define FU_WS2   (64 * 132)
#define FU_SA    (FU_WS2 + 128 * 24)
#define FU_SD    (FU_SA + 16)
#define FU_SE    (FU_SD + 16)
#define FU_SS    (FU_SE + 8 * STASH1 * 4)
#define FU_SMEM  ((FU_SS + 8 * STASH1) * 4)

__global__ void __launch_bounds__(256) k_agg1g2(
    const float* __restrict__ b1, const float* __restrict__ W2,
    const float* __restrict__ as2, const float* __restrict__ ad2) {
    extern __shared__ float sm[];
    float* hs = sm + FU_HS;
    float* ws2 = sm + FU_WS2;
    float* sa = sm + FU_SA;
    float* sd = sm + FU_SD;
    int tid = threadIdx.x;
    int lane = tid & 31, w = tid >> 5;
    float* se = sm + FU_SE + w * (STASH1 * 4);
    int* ss = (int*)(sm + FU_SS) + w * STASH1;
    int n0 = blockIdx.x * 64;

    for (int i = tid; i < FIN * NCLS; i += 256) {
        int k = i >> 4, nn = i & 15;
        ws2[k * 24 + nn] = totf32(W2[i]);
    }
    if (tid < 16) { sa[tid] = as2[tid]; sd[tid] = ad2[tid]; }

    float4 bb = __ldg((const float4*)&b1[lane * 4]);

    // ---- Phase A: aggregate 8 nodes per warp ----
    for (int j = 0; j < 8; j++) {
        int r = j * 8 + w;
        int n = n0 + r;
        if (n >= NN) break;
        int base = g_rowptr[n];
        int deg = g_rowptr[n + 1] - base;
        int tot = deg + 1;
        float4 ald = *(const float4*)&g_ald1[n * 4];
        bool st = (tot <= STASH1);

        float d0 = 0.f, d1 = 0.f, d2 = 0.f, d3 = 0.f;
        if (st) {
            for (int i = lane; i < tot; i += 32) {
                int s = (i < deg) ? g_srcsorted[base + i] : n;
                ss[i] = s;
                float4 as = *(const float4*)&g_als1[s * 4];
                float x0 = __expf(lrelu(as.x + ald.x));
                float x1 = __expf(lrelu(as.y + ald.y));
                float x2 = __expf(lrelu(as.z + ald.z));
                float x3 = __expf(lrelu(as.w + ald.w));
                d0 += x0; d1 += x1; d2 += x2; d3 += x3;
                *(float4*)&se[i * 4] = make_float4(x0, x1, x2, x3);
            }
        } else {
            for (int i = lane; i < tot; i += 32) {
                int s = (i < deg) ? g_srcsorted[base + i] : n;
                float4 as = *(const float4*)&g_als1[s * 4];
                d0 += __expf(lrelu(as.x + ald.x));
                d1 += __expf(lrelu(as.y + ald.y));
                d2 += __expf(lrelu(as.z + ald.z));
                d3 += __expf(lrelu(as.w + ald.w));
            }
        }
#pragma unroll
        for (int o = 16; o >= 1; o >>= 1) {
            d0 += __shfl_xor_sync(0xffffffffu, d0, o);
            d1 += __shfl_xor_sync(0xffffffffu, d1, o);
            d2 += __shfl_xor_sync(0xffffffffu, d2, o);
            d3 += __shfl_xor_sync(0xffffffffu, d3, o);
        }
        __syncwarp();

        int head = lane >> 3;
        float dh = head == 0 ? d0 : (head == 1 ? d1 : (head == 2 ? d2 : d3));
        float inv = 1.f / dh;

        float a0 = 0.f, a1 = 0.f, a2 = 0.f, a3 = 0.f;
        if (st) {
#pragma unroll 4
            for (int i = 0; i < tot; i++) {
                float alpha = se[i * 4 + head] * inv;
                int s = ss[i];
                uint2 raw = *(const uint2*)&g_h1h[(size_t)s * C1 + lane * 4];
                float2 f0 = __half22float2(*reinterpret_cast<__half2*>(&raw.x));
                float2 f1 = __half22float2(*reinterpret_cast<__half2*>(&raw.y));
                a0 += f0.x * alpha; a1 += f0.y * alpha;
                a2 += f1.x * alpha; a3 += f1.y * alpha;
            }
        } else {
            for (int i = 0; i < tot; i++) {
                int s = (i < deg) ? g_srcsorted[base + i] : n;
                float4 as = *(const float4*)&g_als1[s * 4];
                float ev = head == 0 ? (as.x + ald.x) : head == 1 ? (as.y + ald.y)
                         : head == 2 ? (as.z + ald.z) : (as.w + ald.w);
                float alpha = __expf(lrelu(ev)) * inv;
                uint2 raw = *(const uint2*)&g_h1h[(size_t)s * C1 + lane * 4];
                float2 f0 = __half22float2(*reinterpret_cast<__half2*>(&raw.x));
                float2 f1 = __half22float2(*reinterpret_cast<__half2*>(&raw.y));
                a0 += f0.x * alpha; a1 += f0.y * alpha;
                a2 += f1.x * alpha; a3 += f1.y * alpha;
            }
        }

        float v0 = a0 + bb.x, v1 = a1 + bb.y, v2 = a2 + bb.z, v3 = a3 + bb.w;
        v0 = v0 > 0.f ? v0 : (__expf(v0) - 1.f);
        v1 = v1 > 0.f ? v1 : (__expf(v1) - 1.f);
        v2 = v2 > 0.f ? v2 : (__expf(v2) - 1.f);
        v3 = v3 > 0.f ? v3 : (__expf(v3) - 1.f);
        *(float4*)&hs[r * 132 + lane * 4] =
            make_float4(totf32(v0), totf32(v1), totf32(v2), totf32(v3));
    }
    __syncthreads();

    // ---- Phase B: tf32 MMA gemm2 + fused al2 (warps 0-3) ----
    if (w < 4) {
        int g = lane >> 2, q = lane & 3;
        int r0 = w * 16;
        float c[2][4];
        c[0][0] = c[0][1] = c[0][2] = c[0][3] = 0.f;
        c[1][0] = c[1][1] = c[1][2] = c[1][3] = 0.f;

#pragma unroll
        for (int t = 0; t < 16; t++) {
            int k0 = t * 8;
            uint32_t a0 = __float_as_uint(hs[(r0 + g) * 132 + k0 + q]);
            uint32_t a1 = __float_as_uint(hs[(r0 + g + 8) * 132 + k0 + q]);
            uint32_t a2 = __float_as_uint(hs[(r0 + g) * 132 + k0 + q + 4]);
            uint32_t a3 = __float_as_uint(hs[(r0 + g + 8) * 132 + k0 + q + 4]);
#pragma unroll
            for (int nt = 0; nt < 2; nt++) {
                uint32_t b0 = __float_as_uint(ws2[(k0 + q) * 24 + nt * 8 + g]);
                uint32_t b1 = __float_as_uint(ws2[(k0 + q + 4) * 24 + nt * 8 + g]);
                mma_tf32(c[nt][0], c[nt][1], c[nt][2], c[nt][3], a0, a1, a2, a3, b0, b1);
            }
        }

        int row0 = n0 + r0 + g, row1 = row0 + 8;
        float s0 = 0.f, e0 = 0.f, s1 = 0.f, e1 = 0.f;
#pragma unroll
        for (int nt = 0; nt < 2; nt++) {
            int col = nt * 8 + 2 * q;
            if (row0 < NN) *(float2*)&g_h2[row0 * NCLS + col] = make_float2(c[nt][0], c[nt][1]);
            if (row1 < NN) *(float2*)&g_h2[row1 * NCLS + col] = make_float2(c[nt][2], c[nt][3]);
            float wa0 = sa[col], wa1 = sa[col + 1];
            float wd0 = sd[col], wd1 = sd[col + 1];
            s0 += c[nt][0] * wa0 + c[nt][1] * wa1;
            e0 += c[nt][0] * wd0 + c[nt][1] * wd1;
            s1 += c[nt][2] * wa0 + c[nt][3] * wa1;
            e1 += c[nt][2] * wd0 + c[nt][3] * wd1;
        }
        s0 += __shfl_xor_sync(0xffffffffu, s0, 1); s0 += __shfl_xor_sync(0xffffffffu, s0, 2);
        e0 += __shfl_xor_sync(0xffffffffu, e0, 1); e0 += __shfl_xor_sync(0xffffffffu, e0, 2);
        s1 += __shfl_xor_sync(0xffffffffu, s1, 1); s1 += __shfl_xor_sync(0xffffffffu, s1, 2);
        e1 += __shfl_xor_sync(0xffffffffu, e1, 1); e1 += __shfl_xor_sync(0xffffffffu, e1, 2);
        if (q == 0) {
            if (row0 < NN) { g_als2[row0] = s0; g_ald2[row0] = e0; }
            if (row1 < NN) { g_als2[row1] = s1; g_ald2[row1] = e1; }
        }
    }
}

// ---------------- layer-2 softmax-aggregate: 2 nodes/warp, 16 lanes each ----------------
__global__ void k_agg2(const float* __restrict__ b2, float* __restrict__ out) {
    __shared__ float se[8][2][STASH2];
    __shared__ int ss[8][2][STASH2];
    int lane = threadIdx.x & 31, w = threadIdx.x >> 5;
    int half = lane >> 4, sub = lane & 15;
    int n = blockIdx.x * 16 + w * 2 + half;
    if (n >= NN) return;
    int base = g_rowptr[n];
    int deg = g_rowptr[n + 1] - base;
    int tot = deg + 1;
    float ald = g_ald2[n];
    bool st = (tot <= STASH2);
    float* sew = se[w][half];
    int* ssw = ss[w][half];

    float den = 0.f;
    if (st) {
        for (int i = sub; i < tot; i += 16) {
            int s = (i < deg) ? g_srcsorted[base + i] : n;
            ssw[i] = s;
            float ex = __expf(lrelu(g_als2[s] + ald));
            sew[i] = ex;
            den += ex;
        }
    } else {
        for (int i = sub; i < tot; i += 16) {
            int s = (i < deg) ? g_srcsorted[base + i] : n;
            den += __expf(lrelu(g_als2[s] + ald));
        }
    }
#pragma unroll
    for (int o = 8; o >= 1; o >>= 1)
        den += __shfl_xor_sync(0xffffffffu, den, o, 16);
    __syncwarp();
    float inv = 1.f / den;

    float acc = 0.f;
    if (st) {
#pragma unroll 4
        for (int i = 0; i < tot; i++) {
            float alpha = sew[i] * inv;
            int s = ssw[i];
            acc += g_h2[s * NCLS + sub] * alpha;
        }
    } else {
        for (int i = 0; i < tot; i++) {
            int s = (i < deg) ? g_srcsorted[base + i] : n;
            float alpha = __expf(lrelu(g_als2[s] + ald)) * inv;
            acc += g_h2[s * NCLS + sub] * alpha;
        }
    }

    float v = acc + __ldg(&b2[sub]);
    float mm = v;
#pragma unroll
    for (int o = 8; o >= 1; o >>= 1)
        mm = fmaxf(mm, __shfl_xor_sync(0xffffffffu, mm, o, 16));
    float ex = __expf(v - mm);
    float sum = ex;
#pragma unroll
    for (int o = 8; o >= 1; o >>= 1)
        sum += __shfl_xor_sync(0xffffffffu, sum, o, 16);
    float res = v - mm - __logf(sum);
    out[n * NCLS + sub] = res;
}

// ---------------- launch ----------------
extern "C" void kernel_launch(void* const* d_in, const int* in_sizes, int n_in,
                              void* d_out, int out_size) {
    const float* x   = (const float*)d_in[0];
    const int*   ei  = (const int*)d_in[1];
    const float* W1  = (const float*)d_in[2];
    const float* as1 = (const float*)d_in[3];
    const float* ad1 = (const float*)d_in[4];
    const float* b1  = (const float*)d_in[5];
    const float* W2  = (const float*)d_in[6];
    const float* as2 = (const float*)d_in[7];
    const float* ad2 = (const float*)d_in[8];
    const float* b2  = (const float*)d_in[9];
    float* out = (float*)d_out;

    static void* cnt_addr = nullptr;
    static cudaStream_t s2 = nullptr;
    static cudaEvent_t evFork = nullptr, evJoin = nullptr;
    if (!cnt_addr) {
        cudaGetSymbolAddress(&cnt_addr, g_cnt);
        cudaFuncSetAttribute(k_gemm1, cudaFuncAttributeMaxDynamicSharedMemorySize, G1_SMEM);
        cudaFuncSetAttribute(k_agg1g2, cudaFuncAttributeMaxDynamicSharedMemorySize, FU_SMEM);
        cudaStreamCreateWithFlags(&s2, cudaStreamNonBlocking);
        cudaEventCreateWithFlags(&evFork, cudaEventDisableTiming);
        cudaEventCreateWithFlags(&evJoin, cudaEventDisableTiming);
    }

    // fork: gemm1 runs on s2 in parallel with CSR build
    cudaEventRecord(evFork, 0);
    cudaStreamWaitEvent(s2, evFork, 0);
    k_gemm1<<<(NN + 63) / 64, 128, G1_SMEM, s2>>>(x, W1, as1, ad1);
    cudaEventRecord(evJoin, s2);

    // CSR build chain on default stream
    cudaMemsetAsync(cnt_addr, 0, (NN + 2) * sizeof(int));
    k_hist<<<(EE / 8 + 255) / 256, 256>>>(ei);
    k_scan<<<NB_SCAN, 1024>>>();
    k_scatter<<<(EE / 8 + 255) / 256, 256>>>(ei);

    // join
    cudaStreamWaitEvent(0, evJoin, 0);
    k_agg1g2<<<(NN + 63) / 64, 256, FU_SMEM>>>(b1, W2, as2, ad2);
    k_agg2<<<(NN + 15) / 16, 256>>>(b2, out);
}